// round 14
// baseline (speedup 1.0000x reference)
#include <cuda_runtime.h>
#include <cstdint>

using u32 = unsigned int;
using u64 = unsigned long long;
#define FULL 0xffffffffu
#define NW 9            // warps per block
#define WSPAN 1088      // floats per warp stage: 16*68 hidden

__device__ __forceinline__ float tanha(float x) {
    float y; asm("tanh.approx.f32 %0, %1;" : "=f"(y) : "f"(x)); return y;
}
__device__ __forceinline__ u32 t32(float v) {
    u32 r; asm("cvt.rna.tf32.f32 %0, %1;" : "=r"(r) : "f"(v)); return r;
}
__device__ __forceinline__ u64 pk2(float lo, float hi) {
    u64 r; asm("mov.b64 %0, {%1, %2};" : "=l"(r) : "f"(lo), "f"(hi)); return r;
}
__device__ __forceinline__ void up2(u64 v, float& a, float& b) {
    asm("mov.b64 {%0, %1}, %2;" : "=f"(a), "=f"(b) : "l"(v));
}
__device__ __forceinline__ u64 fma2(u64 a, u64 b, u64 c) {
    u64 d; asm("fma.rn.f32x2 %0, %1, %2, %3;" : "=l"(d) : "l"(a), "l"(b), "l"(c)); return d;
}
// volatile: keep the per-step x reads in the loop (prevents re-materializing
// the 16-register xs arrays that cap occupancy)
__device__ __forceinline__ void lds2v(float& x0, float& x1, u32 addr) {
    asm volatile("ld.shared.v2.f32 {%0, %1}, [%2];" : "=f"(x0), "=f"(x1) : "r"(addr));
}

// d = a(16x8 tf32) @ b(8x8 tf32) + c
__device__ __forceinline__ void mma8(float d[4], const u32 a[4], const u32 b[2],
                                     const float c[4]) {
    asm("mma.sync.aligned.m16n8k8.row.col.f32.tf32.tf32.f32 "
        "{%0,%1,%2,%3}, {%4,%5,%6,%7}, {%8,%9}, {%10,%11,%12,%13};"
        : "=f"(d[0]), "=f"(d[1]), "=f"(d[2]), "=f"(d[3])
        : "r"(a[0]), "r"(a[1]), "r"(a[2]), "r"(a[3]),
          "r"(b[0]), "r"(b[1]),
          "f"(c[0]), "f"(c[1]), "f"(c[2]), "f"(c[3]));
}

__device__ __forceinline__ void cp16(float* dst_smem, const float* src) {
    u32 daddr = (u32)__cvta_generic_to_shared(dst_smem);
    asm volatile("cp.async.cg.shared.global [%0], [%1], 16;\n"
                 "cp.async.commit_group;" :: "r"(daddr), "l"(src) : "memory");
}

// Accumulator position p holds h component pi(p): lane accum slots == next-step
// A-frag slots, so the recurrence needs no shuffles.
__device__ __forceinline__ int pi_map(int p) {
    return (p < 8) ? ((p >> 1) | ((p & 1) << 2))
                   : (8 | (((p - 8) >> 1)) | ((p & 1) << 2));
}

// B (h-part only) element: col = permuted output col (0..47), k = 0..15
__device__ __forceinline__ float bval_h(const float* w_hh, int col, int k) {
    int grp = col >> 4;
    int g = pi_map(col & 15) + grp * 16;
    return w_hh[g * 16 + k];
}

__global__ void __launch_bounds__(288, 2)
gru_adder_kernel(const float* __restrict__ x,
                 const float* __restrict__ w_ih,   // [48,2]
                 const float* __restrict__ w_hh,   // [48,16]
                 const float* __restrict__ b_ih,   // [48]
                 const float* __restrict__ b_hh,   // [48]
                 const float* __restrict__ w_sum,  // [16]
                 const float* __restrict__ b_sum,  // [1]
                 const float* __restrict__ w_car,  // [16]
                 const float* __restrict__ b_car,  // [1]
                 float* __restrict__ out_hidden,   // [B,4,16]
                 float* __restrict__ out_sums,     // [B,4]
                 float* __restrict__ out_carry,    // [B]
                 float* __restrict__ out_ol,       // [B,5]
                 int Bn)
{
    __shared__ float sb[NW * WSPAN];
    __shared__ float sx[NW * 256];    // per-warp double-buffered x (2 x 512B)

    const int warp = threadIdx.x >> 5;
    const int l = threadIdx.x & 31;
    const int q = l & 3;      // lane quad position
    const int a = l >> 2;     // row group: rows a and a+8

    float* swh = sb + warp * WSPAN;   // hidden stage: 16 rows x 68 (pad: 68%32=4)
    float* sxw = sx + warp * 256;     // x stage: 2 buffers x 16 rows x 8
    const u32 sxbase = (u32)__cvta_generic_to_shared(sxw);

    // ---------- per-lane B fragments (single tf32), h-chunks only ----------
    // r/z tiles PRESCALED by 0.5: sig(x) = 0.5*tanh(0.5x)+0.5
    u32 Bh[4][2][2];
#pragma unroll
    for (int nt = 0; nt < 4; nt++) {
#pragma unroll
        for (int kc = 0; kc < 2; kc++) {
            int col = nt * 8 + a;
            Bh[nt][kc][0] = t32(0.5f * bval_h(w_hh, col, kc * 8 + q));
            Bh[nt][kc][1] = t32(0.5f * bval_h(w_hh, col, kc * 8 + q + 4));
        }
    }
    u32 Hh[2][2][2];
#pragma unroll
    for (int ti = 0; ti < 2; ti++) {
#pragma unroll
        for (int kc = 0; kc < 2; kc++) {
            int col = 32 + ti * 8 + a;
            Hh[ti][kc][0] = t32(bval_h(w_hh, col, kc * 8 + q));
            Hh[ti][kc][1] = t32(bval_h(w_hh, col, kc * 8 + q + 4));
        }
    }
    // sum/carry projection tile: col 0 = w_sum, col 1 = w_car, cols 2..7 = 0
    u32 BS[2][2];
#pragma unroll
    for (int kc = 0; kc < 2; kc++) {
        float v0 = 0.0f, v1 = 0.0f;
        if (a == 0) { v0 = w_sum[kc * 8 + q]; v1 = w_sum[kc * 8 + q + 4]; }
        if (a == 1) { v0 = w_car[kc * 8 + q]; v1 = w_car[kc * 8 + q + 4]; }
        BS[kc][0] = t32(v0);
        BS[kc][1] = t32(v1);
    }

    // ---------- per-lane x weights, packed over pr; rz prescaled 0.5 ----------
    u64 wxp0[6], wxp1[6];
#pragma unroll
    for (int nt = 0; nt < 4; nt++) {
        int c0 = nt * 8 + 2 * q, c1 = c0 + 1;
        int g0 = pi_map(c0 & 15) + (c0 >> 4) * 16;
        int g1 = pi_map(c1 & 15) + (c1 >> 4) * 16;
        wxp0[nt] = pk2(0.5f * w_ih[g0 * 2],     0.5f * w_ih[g1 * 2]);
        wxp1[nt] = pk2(0.5f * w_ih[g0 * 2 + 1], 0.5f * w_ih[g1 * 2 + 1]);
    }
#pragma unroll
    for (int ti = 0; ti < 2; ti++) {
        int c0 = (6 + ti) * 8 + 2 * q, c1 = c0 + 1;
        int g0 = pi_map(c0 & 15) + 32;
        int g1 = pi_map(c1 & 15) + 32;
        wxp0[4 + ti] = pk2(w_ih[g0 * 2],     w_ih[g1 * 2]);
        wxp1[4 + ti] = pk2(w_ih[g0 * 2 + 1], w_ih[g1 * 2 + 1]);
    }

    // ---------- per-lane bias init, packed over pr; rz prescaled 0.5 ----------
    u64 cbp[8];
#pragma unroll
    for (int nt = 0; nt < 8; nt++) {
        float vv[2];
#pragma unroll
        for (int pr = 0; pr < 2; pr++) {
            int col = nt * 8 + 2 * q + pr;
            int grp = col >> 4;
            int g = pi_map(col & 15);
            if (grp == 0)      vv[pr] = 0.5f * (b_ih[g] + b_hh[g]);
            else if (grp == 1) vv[pr] = 0.5f * (b_ih[16 + g] + b_hh[16 + g]);
            else if (grp == 2) vv[pr] = b_hh[32 + g];
            else               vv[pr] = b_ih[32 + g];
        }
        cbp[nt] = pk2(vv[0], vv[1]);
    }

    const float bs = b_sum[0];
    const float bc = b_car[0];

    // ---------- persistent loop over 16-row tiles, x double-buffer prefetch ----------
    const int ntiles = Bn >> 4;
    const int nwarp = blockDim.x >> 5;
    const int tstride = gridDim.x * nwarp;
    const int tile0 = blockIdx.x * nwarp + warp;

    if (tile0 < ntiles)
        cp16(sxw + l * 4, x + (size_t)tile0 * 128 + l * 4);

    int buf = 0;
    for (int tile = tile0; tile < ntiles; tile += tstride) {
        const int e0 = tile * 16;
        const int er0 = e0 + a, er1 = e0 + a + 8;

        // wait for this tile's x; prefetch next into the other buffer
        asm volatile("cp.async.wait_group 0;" ::: "memory");
        __syncwarp();
        const int nxt = tile + tstride;
        if (nxt < ntiles)
            cp16(sxw + (buf ^ 1) * 128 + l * 4, x + (size_t)nxt * 128 + l * 4);
        const u32 xb = sxbase + buf * 512;

        // h state: hr0[m]/hr1[m] = h[row][component q+4*(m&1)+8*(m>>1)]
        float hr0[4] = {0.f, 0.f, 0.f, 0.f};
        float hr1[4] = {0.f, 0.f, 0.f, 0.f};

        u32 ahh[2][4];           // A-frag of current h (loop-carried)
        float su0[4], su1[4];    // per-step sum logits (valid in q==0 lanes)
        float ca0, ca1;          // carry logits (valid in q==0 lanes)

#pragma unroll
        for (int t = 0; t < 4; t++) {
            // per-step x from shared (volatile: stays a per-step LDS.64)
            float x00, x01, x10, x11;
            lds2v(x00, x01, xb + (a * 8 + 2 * t) * 4);
            lds2v(x10, x11, xb + ((a + 8) * 8 + 2 * t) * 4);
            const u64 xd00 = pk2(x00, x00);
            const u64 xd01 = pk2(x01, x01);
            const u64 xd10 = pk2(x10, x10);
            const u64 xd11 = pk2(x11, x11);

            // acc init: biases + exact scalar x contribution (f32x2 packed)
            float acc[6][4];
#pragma unroll
            for (int nt = 0; nt < 4; nt++) {
                u64 p0 = fma2(wxp1[nt], xd01, fma2(wxp0[nt], xd00, cbp[nt]));
                u64 p1 = fma2(wxp1[nt], xd11, fma2(wxp0[nt], xd10, cbp[nt]));
                up2(p0, acc[nt][0], acc[nt][1]);
                up2(p1, acc[nt][2], acc[nt][3]);
            }
#pragma unroll
            for (int ti = 0; ti < 2; ti++) {
                up2(cbp[4 + ti], acc[4 + ti][0], acc[4 + ti][1]);
                acc[4 + ti][2] = acc[4 + ti][0];
                acc[4 + ti][3] = acc[4 + ti][1];
            }
            // i_n (pure scalar path, packed)
            float in0[4], in1[4];
#pragma unroll
            for (int ti = 0; ti < 2; ti++) {
                u64 p0 = fma2(wxp1[4 + ti], xd01, fma2(wxp0[4 + ti], xd00, cbp[6 + ti]));
                u64 p1 = fma2(wxp1[4 + ti], xd11, fma2(wxp0[4 + ti], xd10, cbp[6 + ti]));
                up2(p0, in0[ti * 2], in0[ti * 2 + 1]);
                up2(p1, in1[ti * 2], in1[ti * 2 + 1]);
            }

            if (t > 0) {
                // gate MMAs use the A-frag built after last step's h update
#pragma unroll
                for (int nt = 0; nt < 4; nt++) {
#pragma unroll
                    for (int kc = 0; kc < 2; kc++)
                        mma8(acc[nt], ahh[kc], Bh[nt][kc], acc[nt]);
                }
#pragma unroll
                for (int ti = 0; ti < 2; ti++) {
#pragma unroll
                    for (int kc = 0; kc < 2; kc++)
                        mma8(acc[4 + ti], ahh[kc], Hh[ti][kc], acc[4 + ti]);
                }
            }

            // ---------- epilogue: prescaled activations + h update ----------
            //   r*hn = 0.5*(hn + tr*hn); h' = n + 0.5*(d + tz*d), d = h-n
#pragma unroll
            for (int m = 0; m < 4; m++) {
                const int toff = m >> 1, pr = m & 1;
                {
                    float tr = tanha(acc[toff][pr]);
                    float tz = tanha(acc[2 + toff][pr]);
                    float hn = acc[4 + toff][pr];
                    float n = tanha(fmaf(0.5f, fmaf(tr, hn, hn), in0[toff * 2 + pr]));
                    float d = hr0[m] - n;
                    hr0[m] = fmaf(0.5f, fmaf(tz, d, d), n);
                }
                {
                    float tr = tanha(acc[toff][2 + pr]);
                    float tz = tanha(acc[2 + toff][2 + pr]);
                    float hn = acc[4 + toff][2 + pr];
                    float n = tanha(fmaf(0.5f, fmaf(tr, hn, hn), in1[toff * 2 + pr]));
                    float d = hr1[m] - n;
                    hr1[m] = fmaf(0.5f, fmaf(tz, d, d), n);
                }
                const int col = q + ((m & 1) << 2) + ((m >> 1) << 3);
                swh[a * 68 + t * 16 + col] = hr0[m];
                swh[(a + 8) * 68 + t * 16 + col] = hr1[m];
            }

            // ---------- A-frag of new h (feeds sum MMA now, gates next step) ----------
#pragma unroll
            for (int kc = 0; kc < 2; kc++) {
                ahh[kc][0] = t32(hr0[2 * kc]);
                ahh[kc][1] = t32(hr1[2 * kc]);
                ahh[kc][2] = t32(hr0[2 * kc + 1]);
                ahh[kc][3] = t32(hr1[2 * kc + 1]);
            }

            // ---------- sum/carry logits via MMA (q==0 lanes hold cols 0,1) ----------
            float accS[4] = {bs, bc, bs, bc};
            mma8(accS, ahh[0], BS[0], accS);
            mma8(accS, ahh[1], BS[1], accS);
            su0[t] = accS[0];
            su1[t] = accS[2];
            ca0 = accS[1];
            ca1 = accS[3];
        }
        buf ^= 1;

        // ---------- direct logit stores (q==0 lanes own rows a, a+8) ----------
        if (q == 0) {
            float4 s4a = make_float4(su0[0], su0[1], su0[2], su0[3]);
            float4 s4b = make_float4(su1[0], su1[1], su1[2], su1[3]);
            *reinterpret_cast<float4*>(out_sums + (size_t)er0 * 4) = s4a;
            *reinterpret_cast<float4*>(out_sums + (size_t)er1 * 4) = s4b;
            out_carry[er0] = ca0;
            out_carry[er1] = ca1;
            float* o0 = out_ol + (size_t)er0 * 5;   // 20B stride: scalar stores
            o0[0] = s4a.x; o0[1] = s4a.y; o0[2] = s4a.z; o0[3] = s4a.w; o0[4] = ca0;
            float* o1 = out_ol + (size_t)er1 * 5;
            o1[0] = s4b.x; o1[1] = s4b.y; o1[2] = s4b.z; o1[3] = s4b.w; o1[4] = ca1;
        }
        __syncwarp();

        // ---------- coalesced hidden read-back ----------
        float4* oh4 = reinterpret_cast<float4*>(out_hidden + (size_t)e0 * 64);
#pragma unroll
        for (int i = 0; i < 8; i++) {
            int idx = i * 32 + l;
            int row = idx >> 4, c4 = idx & 15;
            oh4[idx] = *reinterpret_cast<float4*>(swh + row * 68 + c4 * 4);
        }

        __syncwarp();   // protect stage buffer before next tile overwrites
    }
}

// ---------------- launch ----------------

extern "C" void kernel_launch(void* const* d_in, const int* in_sizes, int n_in,
                              void* d_out, int out_size)
{
    const float* x     = (const float*)d_in[0];
    const float* w_ih  = (const float*)d_in[1];
    const float* w_hh  = (const float*)d_in[2];
    const float* b_ih  = (const float*)d_in[3];
    const float* b_hh  = (const float*)d_in[4];
    const float* w_sum = (const float*)d_in[5];
    const float* b_sum = (const float*)d_in[6];
    const float* w_car = (const float*)d_in[7];
    const float* b_car = (const float*)d_in[8];

    const int B = in_sizes[0] / 8;   // x is [B, 4, 2]

    float* out = (float*)d_out;
    float* out_hidden = out;                              // B*64
    float* out_sums   = out_hidden + (size_t)B * 64;      // B*4
    float* out_carry  = out_sums + (size_t)B * 4;         // B
    float* out_ol     = out_carry + (size_t)B;            // B*5

    const int threads = 32 * NW;            // 9 warps/block, 2 blocks/SM
    int blocks = 296;
    int maxb = (B / 16 + NW - 1) / NW;
    if (blocks > maxb) blocks = maxb;
    if (blocks < 1) blocks = 1;

    gru_adder_kernel<<<blocks, threads>>>(x, w_ih, w_hh, b_ih, b_hh,
                                          w_sum, b_sum, w_car, b_car,
                                          out_hidden, out_sums, out_carry,
                                          out_ol, B);
}

// round 15
// speedup vs baseline: 1.5515x; 1.5515x over previous
#include <cuda_runtime.h>
#include <cstdint>

using u32 = unsigned int;
using u64 = unsigned long long;
#define FULL 0xffffffffu
#define NW 4             // warps per block
#define WSPAN2 2176      // per-warp hidden stage: 2 tiles x 16 rows x 68

__device__ __forceinline__ float tanha(float x) {
    float y; asm("tanh.approx.f32 %0, %1;" : "=f"(y) : "f"(x)); return y;
}
__device__ __forceinline__ u32 t32(float v) {
    u32 r; asm("cvt.rna.tf32.f32 %0, %1;" : "=r"(r) : "f"(v)); return r;
}
__device__ __forceinline__ u64 pk2(float lo, float hi) {
    u64 r; asm("mov.b64 %0, {%1, %2};" : "=l"(r) : "f"(lo), "f"(hi)); return r;
}
__device__ __forceinline__ void up2(u64 v, float& a, float& b) {
    asm("mov.b64 {%0, %1}, %2;" : "=f"(a), "=f"(b) : "l"(v));
}
__device__ __forceinline__ u64 fma2(u64 a, u64 b, u64 c) {
    u64 d; asm("fma.rn.f32x2 %0, %1, %2, %3;" : "=l"(d) : "l"(a), "l"(b), "l"(c)); return d;
}

// d = a(16x8 tf32) @ b(8x8 tf32) + c
__device__ __forceinline__ void mma8(float d[4], const u32 a[4], const u32 b[2],
                                     const float c[4]) {
    asm("mma.sync.aligned.m16n8k8.row.col.f32.tf32.tf32.f32 "
        "{%0,%1,%2,%3}, {%4,%5,%6,%7}, {%8,%9}, {%10,%11,%12,%13};"
        : "=f"(d[0]), "=f"(d[1]), "=f"(d[2]), "=f"(d[3])
        : "r"(a[0]), "r"(a[1]), "r"(a[2]), "r"(a[3]),
          "r"(b[0]), "r"(b[1]),
          "f"(c[0]), "f"(c[1]), "f"(c[2]), "f"(c[3]));
}

__device__ __forceinline__ void cp16(float* dst_smem, const float* src) {
    u32 daddr = (u32)__cvta_generic_to_shared(dst_smem);
    asm volatile("cp.async.cg.shared.global [%0], [%1], 16;\n"
                 "cp.async.commit_group;" :: "r"(daddr), "l"(src) : "memory");
}

// Accumulator position p holds h component pi(p): lane accum slots == next-step
// A-frag slots, so the recurrence needs no shuffles.
__device__ __forceinline__ int pi_map(int p) {
    return (p < 8) ? ((p >> 1) | ((p & 1) << 2))
                   : (8 | (((p - 8) >> 1)) | ((p & 1) << 2));
}

// B (h-part only) element: col = permuted output col (0..47), k = 0..15
__device__ __forceinline__ float bval_h(const float* w_hh, int col, int k) {
    int grp = col >> 4;
    int g = pi_map(col & 15) + grp * 16;
    return w_hh[g * 16 + k];
}

__global__ void __launch_bounds__(128, 3)
gru_adder_kernel(const float* __restrict__ x,
                 const float* __restrict__ w_ih,   // [48,2]
                 const float* __restrict__ w_hh,   // [48,16]
                 const float* __restrict__ b_ih,   // [48]
                 const float* __restrict__ b_hh,   // [48]
                 const float* __restrict__ w_sum,  // [16]
                 const float* __restrict__ b_sum,  // [1]
                 const float* __restrict__ w_car,  // [16]
                 const float* __restrict__ b_car,  // [1]
                 float* __restrict__ out_hidden,   // [B,4,16]
                 float* __restrict__ out_sums,     // [B,4]
                 float* __restrict__ out_carry,    // [B]
                 float* __restrict__ out_ol,       // [B,5]
                 int Bn)
{
    __shared__ float sb[NW * WSPAN2];
    __shared__ float sx[NW * 512];    // per-warp x: 2 buffers x 2 tiles x 128

    const int warp = threadIdx.x >> 5;
    const int l = threadIdx.x & 31;
    const int q = l & 3;      // lane quad position
    const int a = l >> 2;     // row group: rows a and a+8

    float* swhA = sb + warp * WSPAN2;          // tile A hidden stage
    float* swhB = swhA + 1088;                 // tile B hidden stage
    float* sxw  = sx + warp * 512;

    // ---------- per-lane B fragments (single tf32), h-chunks only ----------
    // r/z tiles PRESCALED by 0.5: sig(x) = 0.5*tanh(0.5x)+0.5
    u32 Bh[4][2][2];
#pragma unroll
    for (int nt = 0; nt < 4; nt++) {
#pragma unroll
        for (int kc = 0; kc < 2; kc++) {
            int col = nt * 8 + a;
            Bh[nt][kc][0] = t32(0.5f * bval_h(w_hh, col, kc * 8 + q));
            Bh[nt][kc][1] = t32(0.5f * bval_h(w_hh, col, kc * 8 + q + 4));
        }
    }
    u32 Hh[2][2][2];
#pragma unroll
    for (int ti = 0; ti < 2; ti++) {
#pragma unroll
        for (int kc = 0; kc < 2; kc++) {
            int col = 32 + ti * 8 + a;
            Hh[ti][kc][0] = t32(bval_h(w_hh, col, kc * 8 + q));
            Hh[ti][kc][1] = t32(bval_h(w_hh, col, kc * 8 + q + 4));
        }
    }
    // sum/carry projection tile: col 0 = w_sum, col 1 = w_car, cols 2..7 = 0
    u32 BS[2][2];
#pragma unroll
    for (int kc = 0; kc < 2; kc++) {
        float v0 = 0.0f, v1 = 0.0f;
        if (a == 0) { v0 = w_sum[kc * 8 + q]; v1 = w_sum[kc * 8 + q + 4]; }
        if (a == 1) { v0 = w_car[kc * 8 + q]; v1 = w_car[kc * 8 + q + 4]; }
        BS[kc][0] = t32(v0);
        BS[kc][1] = t32(v1);
    }

    // ---------- per-lane x weights, packed over pr; rz prescaled 0.5 ----------
    u64 wxp0[6], wxp1[6];
#pragma unroll
    for (int nt = 0; nt < 4; nt++) {
        int c0 = nt * 8 + 2 * q, c1 = c0 + 1;
        int g0 = pi_map(c0 & 15) + (c0 >> 4) * 16;
        int g1 = pi_map(c1 & 15) + (c1 >> 4) * 16;
        wxp0[nt] = pk2(0.5f * w_ih[g0 * 2],     0.5f * w_ih[g1 * 2]);
        wxp1[nt] = pk2(0.5f * w_ih[g0 * 2 + 1], 0.5f * w_ih[g1 * 2 + 1]);
    }
#pragma unroll
    for (int ti = 0; ti < 2; ti++) {
        int c0 = (6 + ti) * 8 + 2 * q, c1 = c0 + 1;
        int g0 = pi_map(c0 & 15) + 32;
        int g1 = pi_map(c1 & 15) + 32;
        wxp0[4 + ti] = pk2(w_ih[g0 * 2],     w_ih[g1 * 2]);
        wxp1[4 + ti] = pk2(w_ih[g0 * 2 + 1], w_ih[g1 * 2 + 1]);
    }

    // ---------- per-lane bias init, packed over pr; rz prescaled 0.5 ----------
    u64 cbp[8];
#pragma unroll
    for (int nt = 0; nt < 8; nt++) {
        float vv[2];
#pragma unroll
        for (int pr = 0; pr < 2; pr++) {
            int col = nt * 8 + 2 * q + pr;
            int grp = col >> 4;
            int g = pi_map(col & 15);
            if (grp == 0)      vv[pr] = 0.5f * (b_ih[g] + b_hh[g]);
            else if (grp == 1) vv[pr] = 0.5f * (b_ih[16 + g] + b_hh[16 + g]);
            else if (grp == 2) vv[pr] = b_hh[32 + g];
            else               vv[pr] = b_ih[32 + g];
        }
        cbp[nt] = pk2(vv[0], vv[1]);
    }

    const float bs = b_sum[0];
    const float bc = b_car[0];

    // one GRU step for one 16-row tile (fully inlined; all indices constant)
    auto step = [&](int t, const float* xs0, const float* xs1,
                    float* hr0, float* hr1, u32 (&ahh)[2][4],
                    float* su0, float* su1, float& ca0, float& ca1,
                    float* swh_) {
        const u64 xd00 = pk2(xs0[2 * t], xs0[2 * t]);
        const u64 xd01 = pk2(xs0[2 * t + 1], xs0[2 * t + 1]);
        const u64 xd10 = pk2(xs1[2 * t], xs1[2 * t]);
        const u64 xd11 = pk2(xs1[2 * t + 1], xs1[2 * t + 1]);

        float acc[6][4];
#pragma unroll
        for (int nt = 0; nt < 4; nt++) {
            u64 p0 = fma2(wxp1[nt], xd01, fma2(wxp0[nt], xd00, cbp[nt]));
            u64 p1 = fma2(wxp1[nt], xd11, fma2(wxp0[nt], xd10, cbp[nt]));
            up2(p0, acc[nt][0], acc[nt][1]);
            up2(p1, acc[nt][2], acc[nt][3]);
        }
#pragma unroll
        for (int ti = 0; ti < 2; ti++) {
            up2(cbp[4 + ti], acc[4 + ti][0], acc[4 + ti][1]);
            acc[4 + ti][2] = acc[4 + ti][0];
            acc[4 + ti][3] = acc[4 + ti][1];
        }
        float in0[4], in1[4];
#pragma unroll
        for (int ti = 0; ti < 2; ti++) {
            u64 p0 = fma2(wxp1[4 + ti], xd01, fma2(wxp0[4 + ti], xd00, cbp[6 + ti]));
            u64 p1 = fma2(wxp1[4 + ti], xd11, fma2(wxp0[4 + ti], xd10, cbp[6 + ti]));
            up2(p0, in0[ti * 2], in0[ti * 2 + 1]);
            up2(p1, in1[ti * 2], in1[ti * 2 + 1]);
        }

        if (t > 0) {
#pragma unroll
            for (int nt = 0; nt < 4; nt++) {
#pragma unroll
                for (int kc = 0; kc < 2; kc++)
                    mma8(acc[nt], ahh[kc], Bh[nt][kc], acc[nt]);
            }
#pragma unroll
            for (int ti = 0; ti < 2; ti++) {
#pragma unroll
                for (int kc = 0; kc < 2; kc++)
                    mma8(acc[4 + ti], ahh[kc], Hh[ti][kc], acc[4 + ti]);
            }
        }

        // prescaled activations + h update
        //   r*hn = 0.5*(hn + tr*hn); h' = n + 0.5*(d + tz*d), d = h-n
#pragma unroll
        for (int m = 0; m < 4; m++) {
            const int toff = m >> 1, pr = m & 1;
            {
                float tr = tanha(acc[toff][pr]);
                float tz = tanha(acc[2 + toff][pr]);
                float hn = acc[4 + toff][pr];
                float n = tanha(fmaf(0.5f, fmaf(tr, hn, hn), in0[toff * 2 + pr]));
                float d = hr0[m] - n;
                hr0[m] = fmaf(0.5f, fmaf(tz, d, d), n);
            }
            {
                float tr = tanha(acc[toff][2 + pr]);
                float tz = tanha(acc[2 + toff][2 + pr]);
                float hn = acc[4 + toff][2 + pr];
                float n = tanha(fmaf(0.5f, fmaf(tr, hn, hn), in1[toff * 2 + pr]));
                float d = hr1[m] - n;
                hr1[m] = fmaf(0.5f, fmaf(tz, d, d), n);
            }
            const int col = q + ((m & 1) << 2) + ((m >> 1) << 3);
            swh_[a * 68 + t * 16 + col] = hr0[m];
            swh_[(a + 8) * 68 + t * 16 + col] = hr1[m];
        }

        // A-frag of new h (feeds sum MMA now, gates next step)
#pragma unroll
        for (int kc = 0; kc < 2; kc++) {
            ahh[kc][0] = t32(hr0[2 * kc]);
            ahh[kc][1] = t32(hr1[2 * kc]);
            ahh[kc][2] = t32(hr0[2 * kc + 1]);
            ahh[kc][3] = t32(hr1[2 * kc + 1]);
        }

        // sum/carry logits via MMA (q==0 lanes hold cols 0,1)
        float accS[4] = {bs, bc, bs, bc};
        mma8(accS, ahh[0], BS[0], accS);
        mma8(accS, ahh[1], BS[1], accS);
        su0[t] = accS[0];
        su1[t] = accS[2];
        ca0 = accS[1];
        ca1 = accS[3];
    };

    // ---------- persistent loop over 32-row supertiles ----------
    const int nst = Bn >> 5;
    const int nwarp = blockDim.x >> 5;
    const int tstride = gridDim.x * nwarp;
    const int st0 = blockIdx.x * nwarp + warp;

    if (st0 < nst) {
        cp16(sxw + l * 4,       x + (size_t)st0 * 256 + l * 4);
        cp16(sxw + 128 + l * 4, x + (size_t)st0 * 256 + 128 + l * 4);
    }

    int buf = 0;
    for (int st = st0; st < nst; st += tstride) {
        const int e0 = st * 32;       // tile A rows [e0, e0+16), B [e0+16, e0+32)
        const int eB = e0 + 16;

        asm volatile("cp.async.wait_group 0;" ::: "memory");
        __syncwarp();
        const float* xbuf = sxw + buf * 256;
        float4 a0 = *reinterpret_cast<const float4*>(xbuf + a * 8);
        float4 a1 = *reinterpret_cast<const float4*>(xbuf + a * 8 + 4);
        float4 a2 = *reinterpret_cast<const float4*>(xbuf + (a + 8) * 8);
        float4 a3 = *reinterpret_cast<const float4*>(xbuf + (a + 8) * 8 + 4);
        float4 b0 = *reinterpret_cast<const float4*>(xbuf + 128 + a * 8);
        float4 b1 = *reinterpret_cast<const float4*>(xbuf + 128 + a * 8 + 4);
        float4 b2 = *reinterpret_cast<const float4*>(xbuf + 128 + (a + 8) * 8);
        float4 b3 = *reinterpret_cast<const float4*>(xbuf + 128 + (a + 8) * 8 + 4);
        float xsA0[8] = {a0.x, a0.y, a0.z, a0.w, a1.x, a1.y, a1.z, a1.w};
        float xsA1[8] = {a2.x, a2.y, a2.z, a2.w, a3.x, a3.y, a3.z, a3.w};
        float xsB0[8] = {b0.x, b0.y, b0.z, b0.w, b1.x, b1.y, b1.z, b1.w};
        float xsB1[8] = {b2.x, b2.y, b2.z, b2.w, b3.x, b3.y, b3.z, b3.w};
        __syncwarp();
        const int nxt = st + tstride;
        if (nxt < nst) {
            float* pb = sxw + (buf ^ 1) * 256;
            cp16(pb + l * 4,       x + (size_t)nxt * 256 + l * 4);
            cp16(pb + 128 + l * 4, x + (size_t)nxt * 256 + 128 + l * 4);
        }
        buf ^= 1;

        float hrA0[4] = {0.f, 0.f, 0.f, 0.f}, hrA1[4] = {0.f, 0.f, 0.f, 0.f};
        float hrB0[4] = {0.f, 0.f, 0.f, 0.f}, hrB1[4] = {0.f, 0.f, 0.f, 0.f};
        u32 ahhA[2][4], ahhB[2][4];
        float suA0[4], suA1[4], suB0[4], suB1[4];
        float caA0, caA1, caB0, caB1;

#pragma unroll
        for (int t = 0; t < 4; t++) {
            step(t, xsA0, xsA1, hrA0, hrA1, ahhA, suA0, suA1, caA0, caA1, swhA);
            step(t, xsB0, xsB1, hrB0, hrB1, ahhB, suB0, suB1, caB0, caB1, swhB);
        }

        // ---------- direct logit stores (q==0 lanes own rows a, a+8) ----------
        if (q == 0) {
            const int erA0 = e0 + a, erA1 = e0 + a + 8;
            const int erB0 = eB + a, erB1 = eB + a + 8;
            float4 sA0 = make_float4(suA0[0], suA0[1], suA0[2], suA0[3]);
            float4 sA1 = make_float4(suA1[0], suA1[1], suA1[2], suA1[3]);
            float4 sB0 = make_float4(suB0[0], suB0[1], suB0[2], suB0[3]);
            float4 sB1 = make_float4(suB1[0], suB1[1], suB1[2], suB1[3]);
            *reinterpret_cast<float4*>(out_sums + (size_t)erA0 * 4) = sA0;
            *reinterpret_cast<float4*>(out_sums + (size_t)erA1 * 4) = sA1;
            *reinterpret_cast<float4*>(out_sums + (size_t)erB0 * 4) = sB0;
            *reinterpret_cast<float4*>(out_sums + (size_t)erB1 * 4) = sB1;
            out_carry[erA0] = caA0; out_carry[erA1] = caA1;
            out_carry[erB0] = caB0; out_carry[erB1] = caB1;
            float* o;
            o = out_ol + (size_t)erA0 * 5;
            o[0] = sA0.x; o[1] = sA0.y; o[2] = sA0.z; o[3] = sA0.w; o[4] = caA0;
            o = out_ol + (size_t)erA1 * 5;
            o[0] = sA1.x; o[1] = sA1.y; o[2] = sA1.z; o[3] = sA1.w; o[4] = caA1;
            o = out_ol + (size_t)erB0 * 5;
            o[0] = sB0.x; o[1] = sB0.y; o[2] = sB0.z; o[3] = sB0.w; o[4] = caB0;
            o = out_ol + (size_t)erB1 * 5;
            o[0] = sB1.x; o[1] = sB1.y; o[2] = sB1.z; o[3] = sB1.w; o[4] = caB1;
        }
        __syncwarp();

        // ---------- coalesced hidden read-back (both tiles: 32 rows) ----------
        float4* oh4 = reinterpret_cast<float4*>(out_hidden + (size_t)e0 * 64);
#pragma unroll
        for (int i = 0; i < 16; i++) {
            int idx = i * 32 + l;
            int row = idx >> 4, c4 = idx & 15;       // row 0..31
            float* src = (row < 16) ? (swhA + row * 68 + c4 * 4)
                                    : (swhB + (row - 16) * 68 + c4 * 4);
            oh4[idx] = *reinterpret_cast<float4*>(src);
        }

        __syncwarp();   // protect stage buffers before next supertile
    }
}

// ---------------- launch ----------------

extern "C" void kernel_launch(void* const* d_in, const int* in_sizes, int n_in,
                              void* d_out, int out_size)
{
    const float* x     = (const float*)d_in[0];
    const float* w_ih  = (const float*)d_in[1];
    const float* w_hh  = (const float*)d_in[2];
    const float* b_ih  = (const float*)d_in[3];
    const float* b_hh  = (const float*)d_in[4];
    const float* w_sum = (const float*)d_in[5];
    const float* b_sum = (const float*)d_in[6];
    const float* w_car = (const float*)d_in[7];
    const float* b_car = (const float*)d_in[8];

    const int B = in_sizes[0] / 8;   // x is [B, 4, 2]

    float* out = (float*)d_out;
    float* out_hidden = out;                              // B*64
    float* out_sums   = out_hidden + (size_t)B * 64;      // B*4
    float* out_carry  = out_sums + (size_t)B * 4;         // B
    float* out_ol     = out_carry + (size_t)B;            // B*5

    const int threads = 32 * NW;            // 4 warps/block, 3 blocks/SM
    int blocks = 444;
    int maxb = (B / 32 + NW - 1) / NW;
    if (blocks > maxb) blocks = maxb;
    if (blocks < 1) blocks = 1;

    gru_adder_kernel<<<blocks, threads>>>(x, w_ih, w_hh, b_ih, b_hh,
                                          w_sum, b_sum, w_car, b_car,
                                          out_hidden, out_sums, out_carry,
                                          out_ol, B);
}